// round 14
// baseline (speedup 1.0000x reference)
#include <cuda_runtime.h>
#include <cuda_fp16.h>
#include <cstdint>
#include <math.h>

// NT-Xent loss, single fused persistent kernel:
//   phase 1: f32->f16 convert (sliced) + exact f32 positives
//   [grid barrier]
//   phase 2: tournament-symmetric f16-acc HMMA sweep (2 CTAs/SM)
//   [grid barrier]
//   phase 3: distributed combine + last-CTA final mean
// Grid barriers use monotonic ticket counters (no reset -> graph-replay safe).
// Grid is sized nSM * measured_occupancy so every CTA is resident.

#define N2 16384
#define DIM 128
#define NUNITS 8256
#define MAXG 512
#define ROWB 272
#define A_OFF 0
#define B0_OFF 34816
#define B1_OFF 69632
#define SMEM_BYTES 104448

__device__ __half g_zh[N2 * DIM];                      // 4 MB f16 copy
__device__ float g_pos[N2];
__device__ float g_rowpart[MAXG * 2 * 4 * 128];        // [cta][run][wn][row]
__device__ float g_csp[128 * 64 * 2 * 128];            // [rb][d-1][wm][col]
__device__ float g_partials[128];
__device__ unsigned long long g_bar1 = 0, g_bar2 = 0;
__device__ unsigned int g_fin = 0;

__device__ __forceinline__ uint32_t smem_u32(const void* p) {
    uint32_t a;
    asm("{ .reg .u64 t; cvta.to.shared.u64 t, %1; cvt.u32.u64 %0, t; }" : "=r"(a) : "l"(p));
    return a;
}
__device__ __forceinline__ void cp16(uint32_t dst, const void* src) {
    asm volatile("cp.async.cg.shared.global [%0], [%1], 16;" :: "r"(dst), "l"(src));
}
__device__ __forceinline__ void ldm_x4(uint32_t (&r)[4], uint32_t addr) {
    asm volatile("ldmatrix.sync.aligned.m8n8.x4.shared.b16 {%0,%1,%2,%3}, [%4];"
                 : "=r"(r[0]), "=r"(r[1]), "=r"(r[2]), "=r"(r[3]) : "r"(addr));
}
__device__ __forceinline__ void mma_h(uint32_t (&c)[2], const uint32_t (&a)[4],
                                      uint32_t b0, uint32_t b1) {
    asm volatile("mma.sync.aligned.m16n8k16.row.col.f16.f16.f16.f16 "
                 "{%0,%1},{%2,%3,%4,%5},{%6,%7},{%0,%1};"
                 : "+r"(c[0]), "+r"(c[1])
                 : "r"(a[0]), "r"(a[1]), "r"(a[2]), "r"(a[3]), "r"(b0), "r"(b1));
}
__device__ __forceinline__ float ex2(float x) {
    float y; asm("ex2.approx.f32 %0, %1;" : "=f"(y) : "f"(x)); return y;
}
#define C1 2.885390081777927f     // 2*log2(e)

// unit n -> (rb, u); jt = (rb+u) & 127, u=0 is the diag tile.
__device__ __forceinline__ void decode_unit(int n, int& rb, int& u) {
    if (n < 4160) { rb = n / 65; u = n - rb * 65; }
    else { int m = n - 4160; rb = 64 + (m >> 6); u = m & 63; }
}

// Monotonic-ticket grid barrier: safe across graph replays, no reset.
__device__ __forceinline__ void grid_barrier(unsigned long long* ctr, unsigned nct) {
    __threadfence();
    __syncthreads();
    if (threadIdx.x == 0) {
        unsigned long long ticket = atomicAdd(ctr, 1ULL);
        unsigned long long target = (ticket / nct + 1ULL) * nct;
        while (*(volatile unsigned long long*)ctr < target) __nanosleep(64);
    }
    __syncthreads();
    __threadfence();
}

__device__ __forceinline__ void prefetch_tile(uint32_t smbase, const char* gsrc, int tid) {
    #pragma unroll
    for (int i = 0; i < 8; i++) {
        int c = tid + i * 256;
        int r = c >> 4, kc = c & 15;
        cp16(smbase + r * ROWB + kc * 16, gsrc + r * 256 + kc * 16);
    }
}

__device__ __forceinline__ void flush_rows(float (&rs)[8], int cta, int runidx,
                                           int wm, int wn, int l) {
    #pragma unroll
    for (int u = 0; u < 8; u++) {
        rs[u] += __shfl_xor_sync(0xffffffffu, rs[u], 1);
        rs[u] += __shfl_xor_sync(0xffffffffu, rs[u], 2);
    }
    if ((l & 3) == 0) {
        float* dst = g_rowpart + (((size_t)cta * 2 + runidx) * 4 + wn) * 128;
        #pragma unroll
        for (int u = 0; u < 8; u++) {
            int r = wm * 64 + (u >> 1) * 16 + (l >> 2) + 8 * (u & 1);
            dst[r] = rs[u];
        }
    }
    #pragma unroll
    for (int u = 0; u < 8; u++) rs[u] = 0.f;
}

__global__ void __launch_bounds__(256, 2) ntxent_fused_kernel(
        const float* __restrict__ z, float* __restrict__ out) {
    extern __shared__ char sm[];
    const uint32_t s = smem_u32(sm);

    const int G = gridDim.x;
    const int cta = blockIdx.x;
    const int tid = threadIdx.x;
    const int w = tid >> 5, l = tid & 31;
    const int wm = w >> 2, wn = w & 3;

    // ---- phase 1a: f32 -> f16 convert (balanced slice) ----
    {
        const int TOT4 = N2 * DIM / 4;         // 524288 float4 chunks
        int i0 = (int)(((long long)cta * TOT4) / G);
        int i1 = (int)(((long long)(cta + 1) * TOT4) / G);
        for (int i = i0 + tid; i < i1; i += 256) {
            const float4 v = ((const float4*)z)[i];
            __half2 lo = __floats2half2_rn(v.x, v.y);
            __half2 hi = __floats2half2_rn(v.z, v.w);
            uint2 o;
            o.x = *(const uint32_t*)&lo;
            o.y = *(const uint32_t*)&hi;
            ((uint2*)g_zh)[i] = o;
        }
    }
    // ---- phase 1b: exact f32 positives (independent of g_zh) ----
    {
        int r0 = (int)(((long long)cta * N2) / G);
        int r1 = (int)(((long long)(cta + 1) * N2) / G);
        for (int row = r0 + w; row < r1; row += 8) {
            float4 a4 = ((const float4*)(z + (size_t)row * DIM))[l];
            float4 b4 = ((const float4*)(z + (size_t)(row ^ 8192) * DIM))[l];
            float d = fmaf(a4.x, b4.x, fmaf(a4.y, b4.y, fmaf(a4.z, b4.z, a4.w * b4.w)));
            #pragma unroll
            for (int off = 16; off >= 1; off >>= 1)
                d += __shfl_xor_sync(0xffffffffu, d, off);
            if (l == 0) g_pos[row] = 2.f * d;
        }
    }

    grid_barrier(&g_bar1, G);

    // ---- phase 2: tournament HMMA sweep ----
    const int n0 = (int)(((long long)cta * NUNITS) / G);
    const int n1 = (int)(((long long)(cta + 1) * NUNITS) / G);

    const char* zh = (const char*)g_zh;
    const uint32_t laneA = (uint32_t)((l & 15) * ROWB + (l >> 4) * 16);
    const uint32_t laneB = (uint32_t)(((l & 7) + ((l >> 4) << 3)) * ROWB + (((l >> 3) & 1) << 4));
    const uint32_t A_warp = s + A_OFF + (uint32_t)wm * 64 * ROWB + laneA;

    int cur_rb, u0;
    decode_unit(n0, cur_rb, u0);
    prefetch_tile(s + A_OFF, zh + (size_t)cur_rb * 32768, tid);
    prefetch_tile(s + B0_OFF, zh + (size_t)((cur_rb + u0) & 127) * 32768, tid);
    asm volatile("cp.async.commit_group;" ::: "memory");
    asm volatile("cp.async.wait_group 0;" ::: "memory");
    __syncthreads();

    float rs[8];
    #pragma unroll
    for (int u = 0; u < 8; u++) rs[u] = 0.f;
    int runidx = 0;
    int p = 0;

    for (int n = n0; n < n1; n++) {
        int rb, u;
        decode_unit(n, rb, u);

        __syncthreads();
        bool newA = (rb != cur_rb);
        if (newA) {
            flush_rows(rs, cta, runidx, wm, wn, l);
            runidx = 1;
            cur_rb = rb;
            prefetch_tile(s + A_OFF, zh + (size_t)rb * 32768, tid);
        }
        if (n + 1 < n1) {
            int rb2, u2;
            decode_unit(n + 1, rb2, u2);
            prefetch_tile(s + (p ? B0_OFF : B1_OFF),
                          zh + (size_t)((rb2 + u2) & 127) * 32768, tid);
        }
        asm volatile("cp.async.commit_group;" ::: "memory");
        if (newA) asm volatile("cp.async.wait_group 0;" ::: "memory");
        else      asm volatile("cp.async.wait_group 1;" ::: "memory");
        __syncthreads();

        const uint32_t B_warp = s + (p ? B1_OFF : B0_OFF)
                                  + (uint32_t)wn * 32 * ROWB + laneB;

        uint32_t acc[4][4][2];
        #pragma unroll
        for (int mf = 0; mf < 4; mf++)
            #pragma unroll
            for (int nf = 0; nf < 4; nf++) { acc[mf][nf][0] = 0u; acc[mf][nf][1] = 0u; }

        #pragma unroll
        for (int ks = 0; ks < 8; ks++) {
            uint32_t a[4][4], b[2][4];
            #pragma unroll
            for (int mf = 0; mf < 4; mf++)
                ldm_x4(a[mf], A_warp + mf * (16 * ROWB) + ks * 32);
            #pragma unroll
            for (int nh = 0; nh < 2; nh++)
                ldm_x4(b[nh], B_warp + nh * (16 * ROWB) + ks * 32);
            #pragma unroll
            for (int mf = 0; mf < 4; mf++)
                #pragma unroll
                for (int nf = 0; nf < 4; nf++)
                    mma_h(acc[mf][nf], a[mf], b[nf >> 1][(nf & 1) * 2],
                          b[nf >> 1][(nf & 1) * 2 + 1]);
        }

        if (u == 0) {
            #pragma unroll
            for (int mf = 0; mf < 4; mf++)
                #pragma unroll
                for (int nf = 0; nf < 4; nf++) {
                    float2 v0 = __half22float2(*(__half2*)&acc[mf][nf][0]);
                    float2 v1 = __half22float2(*(__half2*)&acc[mf][nf][1]);
                    int r = wm * 64 + mf * 16 + (l >> 2);
                    int c = wn * 32 + nf * 8 + 2 * (l & 3);
                    float e00 = (r == c)         ? 0.f : ex2(fmaf(v0.x, C1, -C1));
                    float e01 = (r == c + 1)     ? 0.f : ex2(fmaf(v0.y, C1, -C1));
                    float e10 = (r + 8 == c)     ? 0.f : ex2(fmaf(v1.x, C1, -C1));
                    float e11 = (r + 8 == c + 1) ? 0.f : ex2(fmaf(v1.y, C1, -C1));
                    rs[mf * 2]     += e00 + e01;
                    rs[mf * 2 + 1] += e10 + e11;
                }
        } else {
            float cs[8];
            #pragma unroll
            for (int v = 0; v < 8; v++) cs[v] = 0.f;
            #pragma unroll
            for (int mf = 0; mf < 4; mf++)
                #pragma unroll
                for (int nf = 0; nf < 4; nf++) {
                    float2 v0 = __half22float2(*(__half2*)&acc[mf][nf][0]);
                    float2 v1 = __half22float2(*(__half2*)&acc[mf][nf][1]);
                    float e00 = ex2(fmaf(v0.x, C1, -C1));
                    float e01 = ex2(fmaf(v0.y, C1, -C1));
                    float e10 = ex2(fmaf(v1.x, C1, -C1));
                    float e11 = ex2(fmaf(v1.y, C1, -C1));
                    rs[mf * 2]     += e00 + e01;
                    rs[mf * 2 + 1] += e10 + e11;
                    cs[nf * 2]     += e00 + e10;
                    cs[nf * 2 + 1] += e01 + e11;
                }
            #pragma unroll
            for (int v = 0; v < 8; v++) {
                cs[v] += __shfl_xor_sync(0xffffffffu, cs[v], 4);
                cs[v] += __shfl_xor_sync(0xffffffffu, cs[v], 8);
                cs[v] += __shfl_xor_sync(0xffffffffu, cs[v], 16);
            }
            if (l < 4) {
                float* dst = g_csp + (((size_t)rb * 64 + (u - 1)) * 2 + wm) * 128;
                #pragma unroll
                for (int v = 0; v < 8; v++) {
                    int c = wn * 32 + (v >> 1) * 8 + 2 * l + (v & 1);
                    dst[c] = cs[v];
                }
            }
        }
        p ^= 1;
    }

    flush_rows(rs, cta, runidx, wm, wn, l);

    grid_barrier(&g_bar2, G);

    // ---- phase 3: combine (first 128 CTAs; j = cta) ----
    if (cta >= 128) return;
    {
        const int j = cta;
        const int r = tid & 127;
        const int sl = tid >> 7;               // 0 or 1
        float sacc = 0.f;

        if (sl == 0) {
            for (int c = 0; c < G; c++) {
                int na = (int)(((long long)c * NUNITS) / G);
                int nb = (int)(((long long)(c + 1) * NUNITS) / G);
                int rb_a, ua, rb_b, ub;
                decode_unit(na, rb_a, ua);
                decode_unit(nb - 1, rb_b, ub);
                if (rb_a == j) {
                    const float* pp = g_rowpart + ((size_t)c * 2 + 0) * 4 * 128;
                    sacc += (pp[r] + pp[128 + r]) + (pp[256 + r] + pp[384 + r]);
                }
                if (rb_b == j && rb_b != rb_a) {
                    const float* pp = g_rowpart + ((size_t)c * 2 + 1) * 4 * 128;
                    sacc += (pp[r] + pp[128 + r]) + (pp[256 + r] + pp[384 + r]);
                }
            }
        }
        #pragma unroll 4
        for (int dd = 0; dd < 32; dd++) {
            int d = sl * 32 + dd + 1;
            int rb = (j - d) & 127;
            if (d <= 63 || rb < 64) {
                const float* pp = g_csp + (((size_t)rb * 64 + (d - 1)) * 2) * 128;
                sacc += pp[r] + pp[128 + r];
            }
        }

        __shared__ float part[2][128];
        __shared__ float red[128];
        part[sl][r] = sacc;
        __syncthreads();
        if (tid < 128) {
            float sum = part[0][tid] + part[1][tid];
            red[tid] = 2.f + logf(sum) - g_pos[j * 128 + tid];
        }
        __syncthreads();
        if (tid == 0) {
            float acc = 0.f;
            #pragma unroll 8
            for (int i = 0; i < 128; i++) acc += red[i];
            g_partials[j] = acc;
            __threadfence();
            unsigned int ticket = atomicAdd(&g_fin, 1u);   // monotonic
            if ((ticket & 127u) == 127u) {
                float tot = 0.f;
                for (int i = 0; i < 128; i++) tot += g_partials[i];
                *out = tot / (float)N2;
            }
        }
    }
}

extern "C" void kernel_launch(void* const* d_in, const int* in_sizes, int n_in,
                              void* d_out, int out_size) {
    const float* z = (const float*)d_in[0];
    float* out = (float*)d_out;

    cudaFuncSetAttribute(ntxent_fused_kernel,
                         cudaFuncAttributeMaxDynamicSharedMemorySize, SMEM_BYTES);

    int nsm = 0, occ = 0;
    cudaDeviceGetAttribute(&nsm, cudaDevAttrMultiProcessorCount, 0);
    cudaOccupancyMaxActiveBlocksPerMultiprocessor(&occ, ntxent_fused_kernel,
                                                  256, SMEM_BYTES);
    if (occ < 1) occ = 1;
    if (occ > 2) occ = 2;
    int grid = nsm * occ;
    if (grid > MAXG) grid = MAXG;
    if (grid < 129) grid = 129;   // combine needs >=128 CTAs (+1 safety)

    ntxent_fused_kernel<<<grid, 256, SMEM_BYTES>>>(z, out);
}

// round 15
// speedup vs baseline: 1.2732x; 1.2732x over previous
#include <cuda_runtime.h>
#include <cuda_fp16.h>
#include <cstdint>
#include <math.h>

// NT-Xent loss, 2 launches:
//   main: f32->f16 convert (sliced) -> grid barrier -> exact positives in
//         cp.async shadow -> tournament-symmetric f16-acc HMMA sweep (2 CTAs/SM)
//   combine: distributed row-sum assembly + loss + last-block mean
// Grid barrier uses a monotonic ticket counter (graph-replay safe, no reset).

#define N2 16384
#define DIM 128
#define NUNITS 8256
#define MAXG 512
#define ROWB 272
#define A_OFF 0
#define B0_OFF 34816
#define B1_OFF 69632
#define SMEM_BYTES 104448

__device__ __half g_zh[N2 * DIM];                      // 4 MB f16 copy
__device__ float g_pos[N2];
__device__ float g_rowpart[MAXG * 2 * 4 * 128];        // [cta][run][wn][row]
__device__ float g_csp[128 * 64 * 2 * 128];            // [rb][d-1][wm][col]
__device__ float g_partials[128];
__device__ unsigned long long g_bar1 = 0;
__device__ int g_cnt = 0;

__device__ __forceinline__ uint32_t smem_u32(const void* p) {
    uint32_t a;
    asm("{ .reg .u64 t; cvta.to.shared.u64 t, %1; cvt.u32.u64 %0, t; }" : "=r"(a) : "l"(p));
    return a;
}
__device__ __forceinline__ void cp16(uint32_t dst, const void* src) {
    asm volatile("cp.async.cg.shared.global [%0], [%1], 16;" :: "r"(dst), "l"(src));
}
__device__ __forceinline__ void ldm_x4(uint32_t (&r)[4], uint32_t addr) {
    asm volatile("ldmatrix.sync.aligned.m8n8.x4.shared.b16 {%0,%1,%2,%3}, [%4];"
                 : "=r"(r[0]), "=r"(r[1]), "=r"(r[2]), "=r"(r[3]) : "r"(addr));
}
__device__ __forceinline__ void mma_h(uint32_t (&c)[2], const uint32_t (&a)[4],
                                      uint32_t b0, uint32_t b1) {
    asm volatile("mma.sync.aligned.m16n8k16.row.col.f16.f16.f16.f16 "
                 "{%0,%1},{%2,%3,%4,%5},{%6,%7},{%0,%1};"
                 : "+r"(c[0]), "+r"(c[1])
                 : "r"(a[0]), "r"(a[1]), "r"(a[2]), "r"(a[3]), "r"(b0), "r"(b1));
}
__device__ __forceinline__ float ex2(float x) {
    float y; asm("ex2.approx.f32 %0, %1;" : "=f"(y) : "f"(x)); return y;
}
#define C1 2.885390081777927f     // 2*log2(e)

// unit n -> (rb, u); jt = (rb+u) & 127, u=0 is the diag tile.
__device__ __forceinline__ void decode_unit(int n, int& rb, int& u) {
    if (n < 4160) { rb = n / 65; u = n - rb * 65; }
    else { int m = n - 4160; rb = 64 + (m >> 6); u = m & 63; }
}

// Monotonic-ticket grid barrier: safe across graph replays, no reset.
__device__ __forceinline__ void grid_barrier(unsigned long long* ctr, unsigned nct) {
    __threadfence();
    __syncthreads();
    if (threadIdx.x == 0) {
        unsigned long long ticket = atomicAdd(ctr, 1ULL);
        unsigned long long target = (ticket / nct + 1ULL) * nct;
        while (*(volatile unsigned long long*)ctr < target) __nanosleep(64);
    }
    __syncthreads();
    __threadfence();
}

__device__ __forceinline__ void prefetch_tile(uint32_t smbase, const char* gsrc, int tid) {
    #pragma unroll
    for (int i = 0; i < 8; i++) {
        int c = tid + i * 256;
        int r = c >> 4, kc = c & 15;
        cp16(smbase + r * ROWB + kc * 16, gsrc + r * 256 + kc * 16);
    }
}

__device__ __forceinline__ void flush_rows(float (&rs)[8], int cta, int runidx,
                                           int wm, int wn, int l) {
    #pragma unroll
    for (int u = 0; u < 8; u++) {
        rs[u] += __shfl_xor_sync(0xffffffffu, rs[u], 1);
        rs[u] += __shfl_xor_sync(0xffffffffu, rs[u], 2);
    }
    if ((l & 3) == 0) {
        float* dst = g_rowpart + (((size_t)cta * 2 + runidx) * 4 + wn) * 128;
        #pragma unroll
        for (int u = 0; u < 8; u++) {
            int r = wm * 64 + (u >> 1) * 16 + (l >> 2) + 8 * (u & 1);
            dst[r] = rs[u];
        }
    }
    #pragma unroll
    for (int u = 0; u < 8; u++) rs[u] = 0.f;
}

__global__ void __launch_bounds__(256, 2) ntxent_main_kernel(const float* __restrict__ z) {
    extern __shared__ char sm[];
    const uint32_t s = smem_u32(sm);

    const int G = gridDim.x;
    const int cta = blockIdx.x;
    const int tid = threadIdx.x;
    const int w = tid >> 5, l = tid & 31;
    const int wm = w >> 2, wn = w & 3;

    // ---- phase 1: f32 -> f16 convert (balanced slice) ----
    {
        const int TOT4 = N2 * DIM / 4;
        int i0 = (int)(((long long)cta * TOT4) / G);
        int i1 = (int)(((long long)(cta + 1) * TOT4) / G);
        for (int i = i0 + tid; i < i1; i += 256) {
            const float4 v = ((const float4*)z)[i];
            __half2 lo = __floats2half2_rn(v.x, v.y);
            __half2 hi = __floats2half2_rn(v.z, v.w);
            uint2 o;
            o.x = *(const uint32_t*)&lo;
            o.y = *(const uint32_t*)&hi;
            ((uint2*)g_zh)[i] = o;
        }
    }
    grid_barrier(&g_bar1, G);

    // ---- phase 2: tournament HMMA sweep (R13 body) ----
    const int n0 = (int)(((long long)cta * NUNITS) / G);
    const int n1 = (int)(((long long)(cta + 1) * NUNITS) / G);

    const char* zh = (const char*)g_zh;
    const uint32_t laneA = (uint32_t)((l & 15) * ROWB + (l >> 4) * 16);
    const uint32_t laneB = (uint32_t)(((l & 7) + ((l >> 4) << 3)) * ROWB + (((l >> 3) & 1) << 4));
    const uint32_t A_warp = s + A_OFF + (uint32_t)wm * 64 * ROWB + laneA;

    int cur_rb, u0;
    decode_unit(n0, cur_rb, u0);
    prefetch_tile(s + A_OFF, zh + (size_t)cur_rb * 32768, tid);
    prefetch_tile(s + B0_OFF, zh + (size_t)((cur_rb + u0) & 127) * 32768, tid);
    asm volatile("cp.async.commit_group;" ::: "memory");

    // exact f32 positives in the cp.async shadow
    {
        int r0 = (int)(((long long)cta * N2) / G);
        int r1 = (int)(((long long)(cta + 1) * N2) / G);
        for (int row = r0 + w; row < r1; row += 8) {
            float4 a4 = ((const float4*)(z + (size_t)row * DIM))[l];
            float4 b4 = ((const float4*)(z + (size_t)(row ^ 8192) * DIM))[l];
            float d = fmaf(a4.x, b4.x, fmaf(a4.y, b4.y, fmaf(a4.z, b4.z, a4.w * b4.w)));
            #pragma unroll
            for (int off = 16; off >= 1; off >>= 1)
                d += __shfl_xor_sync(0xffffffffu, d, off);
            if (l == 0) g_pos[row] = 2.f * d;
        }
    }

    asm volatile("cp.async.wait_group 0;" ::: "memory");
    __syncthreads();

    float rs[8];
    #pragma unroll
    for (int u = 0; u < 8; u++) rs[u] = 0.f;
    int runidx = 0;
    int p = 0;

    for (int n = n0; n < n1; n++) {
        int rb, u;
        decode_unit(n, rb, u);

        __syncthreads();
        bool newA = (rb != cur_rb);
        if (newA) {
            flush_rows(rs, cta, runidx, wm, wn, l);
            runidx = 1;
            cur_rb = rb;
            prefetch_tile(s + A_OFF, zh + (size_t)rb * 32768, tid);
        }
        if (n + 1 < n1) {
            int rb2, u2;
            decode_unit(n + 1, rb2, u2);
            prefetch_tile(s + (p ? B0_OFF : B1_OFF),
                          zh + (size_t)((rb2 + u2) & 127) * 32768, tid);
        }
        asm volatile("cp.async.commit_group;" ::: "memory");
        if (newA) asm volatile("cp.async.wait_group 0;" ::: "memory");
        else      asm volatile("cp.async.wait_group 1;" ::: "memory");
        __syncthreads();

        const uint32_t B_warp = s + (p ? B1_OFF : B0_OFF)
                                  + (uint32_t)wn * 32 * ROWB + laneB;

        uint32_t acc[4][4][2];
        #pragma unroll
        for (int mf = 0; mf < 4; mf++)
            #pragma unroll
            for (int nf = 0; nf < 4; nf++) { acc[mf][nf][0] = 0u; acc[mf][nf][1] = 0u; }

        #pragma unroll
        for (int ks = 0; ks < 8; ks++) {
            uint32_t a[4][4], b[2][4];
            #pragma unroll
            for (int mf = 0; mf < 4; mf++)
                ldm_x4(a[mf], A_warp + mf * (16 * ROWB) + ks * 32);
            #pragma unroll
            for (int nh = 0; nh < 2; nh++)
                ldm_x4(b[nh], B_warp + nh * (16 * ROWB) + ks * 32);
            #pragma unroll
            for (int mf = 0; mf < 4; mf++)
                #pragma unroll
                for (int nf = 0; nf < 4; nf++)
                    mma_h(acc[mf][nf], a[mf], b[nf >> 1][(nf & 1) * 2],
                          b[nf >> 1][(nf & 1) * 2 + 1]);
        }

        if (u == 0) {
            #pragma unroll
            for (int mf = 0; mf < 4; mf++)
                #pragma unroll
                for (int nf = 0; nf < 4; nf++) {
                    float2 v0 = __half22float2(*(__half2*)&acc[mf][nf][0]);
                    float2 v1 = __half22float2(*(__half2*)&acc[mf][nf][1]);
                    int r = wm * 64 + mf * 16 + (l >> 2);
                    int c = wn * 32 + nf * 8 + 2 * (l & 3);
                    float e00 = (r == c)         ? 0.f : ex2(fmaf(v0.x, C1, -C1));
                    float e01 = (r == c + 1)     ? 0.f : ex2(fmaf(v0.y, C1, -C1));
                    float e10 = (r + 8 == c)     ? 0.f : ex2(fmaf(v1.x, C1, -C1));
                    float e11 = (r + 8 == c + 1) ? 0.f : ex2(fmaf(v1.y, C1, -C1));
                    rs[mf * 2]     += e00 + e01;
                    rs[mf * 2 + 1] += e10 + e11;
                }
        } else {
            float cs[8];
            #pragma unroll
            for (int v = 0; v < 8; v++) cs[v] = 0.f;
            #pragma unroll
            for (int mf = 0; mf < 4; mf++)
                #pragma unroll
                for (int nf = 0; nf < 4; nf++) {
                    float2 v0 = __half22float2(*(__half2*)&acc[mf][nf][0]);
                    float2 v1 = __half22float2(*(__half2*)&acc[mf][nf][1]);
                    float e00 = ex2(fmaf(v0.x, C1, -C1));
                    float e01 = ex2(fmaf(v0.y, C1, -C1));
                    float e10 = ex2(fmaf(v1.x, C1, -C1));
                    float e11 = ex2(fmaf(v1.y, C1, -C1));
                    rs[mf * 2]     += e00 + e01;
                    rs[mf * 2 + 1] += e10 + e11;
                    cs[nf * 2]     += e00 + e10;
                    cs[nf * 2 + 1] += e01 + e11;
                }
            #pragma unroll
            for (int v = 0; v < 8; v++) {
                cs[v] += __shfl_xor_sync(0xffffffffu, cs[v], 4);
                cs[v] += __shfl_xor_sync(0xffffffffu, cs[v], 8);
                cs[v] += __shfl_xor_sync(0xffffffffu, cs[v], 16);
            }
            if (l < 4) {
                float* dst = g_csp + (((size_t)rb * 64 + (u - 1)) * 2 + wm) * 128;
                #pragma unroll
                for (int v = 0; v < 8; v++) {
                    int c = wn * 32 + (v >> 1) * 8 + 2 * l + (v & 1);
                    dst[c] = cs[v];
                }
            }
        }
        p ^= 1;
    }

    flush_rows(rs, cta, runidx, wm, wn, l);
}

// 512 threads: slice sl covers a quarter of the CTA-scan and d-range.
__global__ void __launch_bounds__(512) combine_kernel(float* __restrict__ out, int G) {
    const int j = blockIdx.x;
    const int tid = threadIdx.x;
    const int r = tid & 127;
    const int sl = tid >> 7;
    float s = 0.f;

    int c0 = (sl * G) / 4, c1 = ((sl + 1) * G) / 4;
    for (int c = c0; c < c1; c++) {
        int na = (int)(((long long)c * NUNITS) / G);
        int nb = (int)(((long long)(c + 1) * NUNITS) / G);
        int rb_a, ua, rb_b, ub;
        decode_unit(na, rb_a, ua);
        decode_unit(nb - 1, rb_b, ub);
        if (rb_a == j) {
            const float* p = g_rowpart + ((size_t)c * 2 + 0) * 4 * 128;
            s += (p[r] + p[128 + r]) + (p[256 + r] + p[384 + r]);
        }
        if (rb_b == j && rb_b != rb_a) {
            const float* p = g_rowpart + ((size_t)c * 2 + 1) * 4 * 128;
            s += (p[r] + p[128 + r]) + (p[256 + r] + p[384 + r]);
        }
    }
    #pragma unroll 4
    for (int dd = 0; dd < 16; dd++) {
        int d = sl * 16 + dd + 1;
        int rb = (j - d) & 127;
        if (d <= 63 || rb < 64) {
            const float* p = g_csp + (((size_t)rb * 64 + (d - 1)) * 2) * 128;
            s += p[r] + p[128 + r];
        }
    }

    __shared__ float part[4][128];
    __shared__ float red[128];
    part[sl][r] = s;
    __syncthreads();
    if (tid < 128) {
        float sum = (part[0][tid] + part[1][tid]) + (part[2][tid] + part[3][tid]);
        red[tid] = 2.f + logf(sum) - g_pos[j * 128 + tid];
    }
    __syncthreads();
    if (tid == 0) {
        float acc = 0.f;
        #pragma unroll 8
        for (int i = 0; i < 128; i++) acc += red[i];
        g_partials[j] = acc;
        __threadfence();
        int old = atomicAdd(&g_cnt, 1);
        if ((old & 127) == 127) {
            float tot = 0.f;
            for (int i = 0; i < 128; i++) tot += g_partials[i];
            *out = tot / (float)N2;
        }
    }
}

extern "C" void kernel_launch(void* const* d_in, const int* in_sizes, int n_in,
                              void* d_out, int out_size) {
    const float* z = (const float*)d_in[0];
    float* out = (float*)d_out;

    cudaFuncSetAttribute(ntxent_main_kernel,
                         cudaFuncAttributeMaxDynamicSharedMemorySize, SMEM_BYTES);

    int nsm = 0, occ = 0;
    cudaDeviceGetAttribute(&nsm, cudaDevAttrMultiProcessorCount, 0);
    cudaOccupancyMaxActiveBlocksPerMultiprocessor(&occ, ntxent_main_kernel,
                                                  256, SMEM_BYTES);
    if (occ < 1) occ = 1;
    if (occ > 2) occ = 2;
    int grid = nsm * occ;
    if (grid > MAXG) grid = MAXG;

    ntxent_main_kernel<<<grid, 256, SMEM_BYTES>>>(z);
    combine_kernel<<<128, 512>>>(out, grid);
}

// round 16
// speedup vs baseline: 1.3555x; 1.0647x over previous
#include <cuda_runtime.h>
#include <cuda_fp16.h>
#include <cstdint>
#include <math.h>

// NT-Xent loss, 2 launches, compile-time grid (304 = 152 SMs x 2 CTAs):
//   main: f32->f16 convert (sliced) -> grid barrier -> exact positives in
//         cp.async shadow -> tournament-symmetric f16-acc HMMA sweep
//   combine: distributed row-sum assembly + loss + last-block mean
// Grid barrier: monotonic ticket counter (graph-replay safe). Residency of
// 304 CTAs at (256 thr, 2/SM) proven by the R14 full-persistent run.

#define N2 16384
#define DIM 128
#define NUNITS 8256
#define GRID_MAIN 304
#define ROWB 272
#define A_OFF 0
#define B0_OFF 34816
#define B1_OFF 69632
#define SMEM_BYTES 104448

__device__ __half g_zh[N2 * DIM];                      // 4 MB f16 copy
__device__ float g_pos[N2];
__device__ float g_rowpart[GRID_MAIN * 2 * 4 * 128];   // [cta][run][wn][row]
__device__ float g_csp[128 * 64 * 2 * 128];            // [rb][d-1][wm][col]
__device__ float g_partials[128];
__device__ unsigned long long g_bar1 = 0;
__device__ int g_cnt = 0;

__device__ __forceinline__ uint32_t smem_u32(const void* p) {
    uint32_t a;
    asm("{ .reg .u64 t; cvta.to.shared.u64 t, %1; cvt.u32.u64 %0, t; }" : "=r"(a) : "l"(p));
    return a;
}
__device__ __forceinline__ void cp16(uint32_t dst, const void* src) {
    asm volatile("cp.async.cg.shared.global [%0], [%1], 16;" :: "r"(dst), "l"(src));
}
__device__ __forceinline__ void ldm_x4(uint32_t (&r)[4], uint32_t addr) {
    asm volatile("ldmatrix.sync.aligned.m8n8.x4.shared.b16 {%0,%1,%2,%3}, [%4];"
                 : "=r"(r[0]), "=r"(r[1]), "=r"(r[2]), "=r"(r[3]) : "r"(addr));
}
__device__ __forceinline__ void mma_h(uint32_t (&c)[2], const uint32_t (&a)[4],
                                      uint32_t b0, uint32_t b1) {
    asm volatile("mma.sync.aligned.m16n8k16.row.col.f16.f16.f16.f16 "
                 "{%0,%1},{%2,%3,%4,%5},{%6,%7},{%0,%1};"
                 : "+r"(c[0]), "+r"(c[1])
                 : "r"(a[0]), "r"(a[1]), "r"(a[2]), "r"(a[3]), "r"(b0), "r"(b1));
}
__device__ __forceinline__ float ex2(float x) {
    float y; asm("ex2.approx.f32 %0, %1;" : "=f"(y) : "f"(x)); return y;
}
#define C1 2.885390081777927f     // 2*log2(e)

// unit n -> (rb, u); jt = (rb+u) & 127, u=0 is the diag tile.
__device__ __forceinline__ void decode_unit(int n, int& rb, int& u) {
    if (n < 4160) { rb = n / 65; u = n - rb * 65; }
    else { int m = n - 4160; rb = 64 + (m >> 6); u = m & 63; }
}

// Monotonic-ticket grid barrier: safe across graph replays, no reset.
__device__ __forceinline__ void grid_barrier(unsigned long long* ctr, unsigned nct) {
    __threadfence();
    __syncthreads();
    if (threadIdx.x == 0) {
        unsigned long long ticket = atomicAdd(ctr, 1ULL);
        unsigned long long target = (ticket / nct + 1ULL) * nct;
        while (*(volatile unsigned long long*)ctr < target) __nanosleep(64);
    }
    __syncthreads();
    __threadfence();
}

__device__ __forceinline__ void prefetch_tile(uint32_t smbase, const char* gsrc, int tid) {
    #pragma unroll
    for (int i = 0; i < 8; i++) {
        int c = tid + i * 256;
        int r = c >> 4, kc = c & 15;
        cp16(smbase + r * ROWB + kc * 16, gsrc + r * 256 + kc * 16);
    }
}

__device__ __forceinline__ void flush_rows(float (&rs)[8], int cta, int runidx,
                                           int wm, int wn, int l) {
    #pragma unroll
    for (int u = 0; u < 8; u++) {
        rs[u] += __shfl_xor_sync(0xffffffffu, rs[u], 1);
        rs[u] += __shfl_xor_sync(0xffffffffu, rs[u], 2);
    }
    if ((l & 3) == 0) {
        float* dst = g_rowpart + (((size_t)cta * 2 + runidx) * 4 + wn) * 128;
        #pragma unroll
        for (int u = 0; u < 8; u++) {
            int r = wm * 64 + (u >> 1) * 16 + (l >> 2) + 8 * (u & 1);
            dst[r] = rs[u];
        }
    }
    #pragma unroll
    for (int u = 0; u < 8; u++) rs[u] = 0.f;
}

__global__ void __launch_bounds__(256, 2) ntxent_main_kernel(const float* __restrict__ z) {
    extern __shared__ char sm[];
    const uint32_t s = smem_u32(sm);

    const int cta = blockIdx.x;
    const int tid = threadIdx.x;
    const int w = tid >> 5, l = tid & 31;
    const int wm = w >> 2, wn = w & 3;

    // ---- phase 1: f32 -> f16 convert (balanced slice, compile-time grid) ----
    {
        const int TOT4 = N2 * DIM / 4;
        int i0 = (cta * (TOT4 / 16)) / (GRID_MAIN / 16);          // exact: TOT4 % 304 != 0
        i0 = (int)(((long long)cta * TOT4) / GRID_MAIN);          // constant divisor
        int i1 = (int)(((long long)(cta + 1) * TOT4) / GRID_MAIN);
        for (int i = i0 + tid; i < i1; i += 256) {
            const float4 v = ((const float4*)z)[i];
            __half2 lo = __floats2half2_rn(v.x, v.y);
            __half2 hi = __floats2half2_rn(v.z, v.w);
            uint2 o;
            o.x = *(const uint32_t*)&lo;
            o.y = *(const uint32_t*)&hi;
            ((uint2*)g_zh)[i] = o;
        }
    }
    grid_barrier(&g_bar1, GRID_MAIN);

    // ---- phase 2: tournament HMMA sweep ----
    const int n0 = (int)(((long long)cta * NUNITS) / GRID_MAIN);
    const int n1 = (int)(((long long)(cta + 1) * NUNITS) / GRID_MAIN);

    const char* zh = (const char*)g_zh;
    const uint32_t laneA = (uint32_t)((l & 15) * ROWB + (l >> 4) * 16);
    const uint32_t laneB = (uint32_t)(((l & 7) + ((l >> 4) << 3)) * ROWB + (((l >> 3) & 1) << 4));
    const uint32_t A_warp = s + A_OFF + (uint32_t)wm * 64 * ROWB + laneA;

    int cur_rb, u0;
    decode_unit(n0, cur_rb, u0);
    prefetch_tile(s + A_OFF, zh + (size_t)cur_rb * 32768, tid);
    prefetch_tile(s + B0_OFF, zh + (size_t)((cur_rb + u0) & 127) * 32768, tid);
    asm volatile("cp.async.commit_group;" ::: "memory");

    // exact f32 positives in the cp.async shadow
    {
        int r0 = (int)(((long long)cta * N2) / GRID_MAIN);
        int r1 = (int)(((long long)(cta + 1) * N2) / GRID_MAIN);
        for (int row = r0 + w; row < r1; row += 8) {
            float4 a4 = ((const float4*)(z + (size_t)row * DIM))[l];
            float4 b4 = ((const float4*)(z + (size_t)(row ^ 8192) * DIM))[l];
            float d = fmaf(a4.x, b4.x, fmaf(a4.y, b4.y, fmaf(a4.z, b4.z, a4.w * b4.w)));
            #pragma unroll
            for (int off = 16; off >= 1; off >>= 1)
                d += __shfl_xor_sync(0xffffffffu, d, off);
            if (l == 0) g_pos[row] = 2.f * d;
        }
    }

    asm volatile("cp.async.wait_group 0;" ::: "memory");
    __syncthreads();

    float rs[8];
    #pragma unroll
    for (int u = 0; u < 8; u++) rs[u] = 0.f;
    int runidx = 0;
    int p = 0;

    for (int n = n0; n < n1; n++) {
        int rb, u;
        decode_unit(n, rb, u);

        __syncthreads();
        bool newA = (rb != cur_rb);
        if (newA) {
            flush_rows(rs, cta, runidx, wm, wn, l);
            runidx = 1;
            cur_rb = rb;
            prefetch_tile(s + A_OFF, zh + (size_t)rb * 32768, tid);
        }
        if (n + 1 < n1) {
            int rb2, u2;
            decode_unit(n + 1, rb2, u2);
            prefetch_tile(s + (p ? B0_OFF : B1_OFF),
                          zh + (size_t)((rb2 + u2) & 127) * 32768, tid);
        }
        asm volatile("cp.async.commit_group;" ::: "memory");
        if (newA) asm volatile("cp.async.wait_group 0;" ::: "memory");
        else      asm volatile("cp.async.wait_group 1;" ::: "memory");
        __syncthreads();

        const uint32_t B_warp = s + (p ? B1_OFF : B0_OFF)
                                  + (uint32_t)wn * 32 * ROWB + laneB;

        uint32_t acc[4][4][2];
        #pragma unroll
        for (int mf = 0; mf < 4; mf++)
            #pragma unroll
            for (int nf = 0; nf < 4; nf++) { acc[mf][nf][0] = 0u; acc[mf][nf][1] = 0u; }

        #pragma unroll
        for (int ks = 0; ks < 8; ks++) {
            uint32_t a[4][4], b[2][4];
            #pragma unroll
            for (int mf = 0; mf < 4; mf++)
                ldm_x4(a[mf], A_warp + mf * (16 * ROWB) + ks * 32);
            #pragma unroll
            for (int nh = 0; nh < 2; nh++)
                ldm_x4(b[nh], B_warp + nh * (16 * ROWB) + ks * 32);
            #pragma unroll
            for (int mf = 0; mf < 4; mf++)
                #pragma unroll
                for (int nf = 0; nf < 4; nf++)
                    mma_h(acc[mf][nf], a[mf], b[nf >> 1][(nf & 1) * 2],
                          b[nf >> 1][(nf & 1) * 2 + 1]);
        }

        if (u == 0) {
            #pragma unroll
            for (int mf = 0; mf < 4; mf++)
                #pragma unroll
                for (int nf = 0; nf < 4; nf++) {
                    float2 v0 = __half22float2(*(__half2*)&acc[mf][nf][0]);
                    float2 v1 = __half22float2(*(__half2*)&acc[mf][nf][1]);
                    int r = wm * 64 + mf * 16 + (l >> 2);
                    int c = wn * 32 + nf * 8 + 2 * (l & 3);
                    float e00 = (r == c)         ? 0.f : ex2(fmaf(v0.x, C1, -C1));
                    float e01 = (r == c + 1)     ? 0.f : ex2(fmaf(v0.y, C1, -C1));
                    float e10 = (r + 8 == c)     ? 0.f : ex2(fmaf(v1.x, C1, -C1));
                    float e11 = (r + 8 == c + 1) ? 0.f : ex2(fmaf(v1.y, C1, -C1));
                    rs[mf * 2]     += e00 + e01;
                    rs[mf * 2 + 1] += e10 + e11;
                }
        } else {
            float cs[8];
            #pragma unroll
            for (int v = 0; v < 8; v++) cs[v] = 0.f;
            #pragma unroll
            for (int mf = 0; mf < 4; mf++)
                #pragma unroll
                for (int nf = 0; nf < 4; nf++) {
                    float2 v0 = __half22float2(*(__half2*)&acc[mf][nf][0]);
                    float2 v1 = __half22float2(*(__half2*)&acc[mf][nf][1]);
                    float e00 = ex2(fmaf(v0.x, C1, -C1));
                    float e01 = ex2(fmaf(v0.y, C1, -C1));
                    float e10 = ex2(fmaf(v1.x, C1, -C1));
                    float e11 = ex2(fmaf(v1.y, C1, -C1));
                    rs[mf * 2]     += e00 + e01;
                    rs[mf * 2 + 1] += e10 + e11;
                    cs[nf * 2]     += e00 + e10;
                    cs[nf * 2 + 1] += e01 + e11;
                }
            #pragma unroll
            for (int v = 0; v < 8; v++) {
                cs[v] += __shfl_xor_sync(0xffffffffu, cs[v], 4);
                cs[v] += __shfl_xor_sync(0xffffffffu, cs[v], 8);
                cs[v] += __shfl_xor_sync(0xffffffffu, cs[v], 16);
            }
            if (l < 4) {
                float* dst = g_csp + (((size_t)rb * 64 + (u - 1)) * 2 + wm) * 128;
                #pragma unroll
                for (int v = 0; v < 8; v++) {
                    int c = wn * 32 + (v >> 1) * 8 + 2 * l + (v & 1);
                    dst[c] = cs[v];
                }
            }
        }
        p ^= 1;
    }

    flush_rows(rs, cta, runidx, wm, wn, l);
}

// 512 threads, compile-time grid: slice sl covers a quarter of the CTA-scan
// and 16 of the 64 d-values. All divisions have constant divisors.
__global__ void __launch_bounds__(512) combine_kernel(float* __restrict__ out) {
    const int j = blockIdx.x;
    const int tid = threadIdx.x;
    const int r = tid & 127;
    const int sl = tid >> 7;
    float s = 0.f;

    const int c0 = (sl * GRID_MAIN) / 4, c1 = ((sl + 1) * GRID_MAIN) / 4;
    for (int c = c0; c < c1; c++) {
        int na = (int)(((long long)c * NUNITS) / GRID_MAIN);
        int nb = (int)(((long long)(c + 1) * NUNITS) / GRID_MAIN);
        int rb_a, ua, rb_b, ub;
        decode_unit(na, rb_a, ua);
        decode_unit(nb - 1, rb_b, ub);
        if (rb_a == j) {
            const float* p = g_rowpart + ((size_t)c * 2 + 0) * 4 * 128;
            s += (p[r] + p[128 + r]) + (p[256 + r] + p[384 + r]);
        }
        if (rb_b == j && rb_b != rb_a) {
            const float* p = g_rowpart + ((size_t)c * 2 + 1) * 4 * 128;
            s += (p[r] + p[128 + r]) + (p[256 + r] + p[384 + r]);
        }
    }
    #pragma unroll 4
    for (int dd = 0; dd < 16; dd++) {
        int d = sl * 16 + dd + 1;
        int rb = (j - d) & 127;
        if (d <= 63 || rb < 64) {
            const float* p = g_csp + (((size_t)rb * 64 + (d - 1)) * 2) * 128;
            s += p[r] + p[128 + r];
        }
    }

    __shared__ float part[4][128];
    __shared__ float red[128];
    part[sl][r] = s;
    __syncthreads();
    if (tid < 128) {
        float sum = (part[0][tid] + part[1][tid]) + (part[2][tid] + part[3][tid]);
        red[tid] = 2.f + logf(sum) - g_pos[j * 128 + tid];
    }
    __syncthreads();
    if (tid == 0) {
        float acc = 0.f;
        #pragma unroll 8
        for (int i = 0; i < 128; i++) acc += red[i];
        g_partials[j] = acc;
        __threadfence();
        int old = atomicAdd(&g_cnt, 1);
        if ((old & 127) == 127) {
            float tot = 0.f;
            for (int i = 0; i < 128; i++) tot += g_partials[i];
            *out = tot / (float)N2;
        }
    }
}

extern "C" void kernel_launch(void* const* d_in, const int* in_sizes, int n_in,
                              void* d_out, int out_size) {
    const float* z = (const float*)d_in[0];
    float* out = (float*)d_out;

    cudaFuncSetAttribute(ntxent_main_kernel,
                         cudaFuncAttributeMaxDynamicSharedMemorySize, SMEM_BYTES);

    ntxent_main_kernel<<<GRID_MAIN, 256, SMEM_BYTES>>>(z);
    combine_kernel<<<128, 512>>>(out);
}

// round 17
// speedup vs baseline: 1.4603x; 1.0773x over previous
#include <cuda_runtime.h>
#include <cuda_fp16.h>
#include <cstdint>
#include <math.h>

// NT-Xent loss, 2 launches, compile-time grid (304 = 152 SMs x 2 CTAs):
//   main: f32->f16 convert (sliced) -> grid barrier -> exact positives in
//         cp.async shadow -> tournament-symmetric f16-acc HMMA sweep
//   combine: closed-form covering-CTA row assembly + loss + last-block mean

#define N2 16384
#define DIM 128
#define NUNITS 8256
#define GRID_MAIN 304
#define ROWB 272
#define A_OFF 0
#define B0_OFF 34816
#define B1_OFF 69632
#define SMEM_BYTES 104448

__device__ __half g_zh[N2 * DIM];                      // 4 MB f16 copy
__device__ float g_pos[N2];
__device__ float g_rowpart[GRID_MAIN * 2 * 4 * 128];   // [cta][run][wn][row]
__device__ float g_csp[128 * 64 * 2 * 128];            // [rb][d-1][wm][col]
__device__ float g_partials[128];
__device__ unsigned long long g_bar1 = 0;
__device__ int g_cnt = 0;

__device__ __forceinline__ uint32_t smem_u32(const void* p) {
    uint32_t a;
    asm("{ .reg .u64 t; cvta.to.shared.u64 t, %1; cvt.u32.u64 %0, t; }" : "=r"(a) : "l"(p));
    return a;
}
__device__ __forceinline__ void cp16(uint32_t dst, const void* src) {
    asm volatile("cp.async.cg.shared.global [%0], [%1], 16;" :: "r"(dst), "l"(src));
}
__device__ __forceinline__ void ldm_x4(uint32_t (&r)[4], uint32_t addr) {
    asm volatile("ldmatrix.sync.aligned.m8n8.x4.shared.b16 {%0,%1,%2,%3}, [%4];"
                 : "=r"(r[0]), "=r"(r[1]), "=r"(r[2]), "=r"(r[3]) : "r"(addr));
}
__device__ __forceinline__ void mma_h(uint32_t (&c)[2], const uint32_t (&a)[4],
                                      uint32_t b0, uint32_t b1) {
    asm volatile("mma.sync.aligned.m16n8k16.row.col.f16.f16.f16.f16 "
                 "{%0,%1},{%2,%3,%4,%5},{%6,%7},{%0,%1};"
                 : "+r"(c[0]), "+r"(c[1])
                 : "r"(a[0]), "r"(a[1]), "r"(a[2]), "r"(a[3]), "r"(b0), "r"(b1));
}
__device__ __forceinline__ float ex2(float x) {
    float y; asm("ex2.approx.f32 %0, %1;" : "=f"(y) : "f"(x)); return y;
}
#define C1 2.885390081777927f     // 2*log2(e)

// unit n -> (rb, u); jt = (rb+u) & 127, u=0 is the diag tile.
__device__ __forceinline__ void decode_unit(int n, int& rb, int& u) {
    if (n < 4160) { rb = n / 65; u = n - rb * 65; }
    else { int m = n - 4160; rb = 64 + (m >> 6); u = m & 63; }
}
__device__ __forceinline__ int unit_n0(int c) {
    return (int)(((long long)c * NUNITS) / GRID_MAIN);
}

// Monotonic-ticket grid barrier: safe across graph replays, no reset.
__device__ __forceinline__ void grid_barrier(unsigned long long* ctr, unsigned nct) {
    __threadfence();
    __syncthreads();
    if (threadIdx.x == 0) {
        unsigned long long ticket = atomicAdd(ctr, 1ULL);
        unsigned long long target = (ticket / nct + 1ULL) * nct;
        while (*(volatile unsigned long long*)ctr < target) __nanosleep(64);
    }
    __syncthreads();
    __threadfence();
}

__device__ __forceinline__ void prefetch_tile(uint32_t smbase, const char* gsrc, int tid) {
    #pragma unroll
    for (int i = 0; i < 8; i++) {
        int c = tid + i * 256;
        int r = c >> 4, kc = c & 15;
        cp16(smbase + r * ROWB + kc * 16, gsrc + r * 256 + kc * 16);
    }
}

__device__ __forceinline__ void flush_rows(float (&rs)[8], int cta, int runidx,
                                           int wm, int wn, int l) {
    #pragma unroll
    for (int u = 0; u < 8; u++) {
        rs[u] += __shfl_xor_sync(0xffffffffu, rs[u], 1);
        rs[u] += __shfl_xor_sync(0xffffffffu, rs[u], 2);
    }
    if ((l & 3) == 0) {
        float* dst = g_rowpart + (((size_t)cta * 2 + runidx) * 4 + wn) * 128;
        #pragma unroll
        for (int u = 0; u < 8; u++) {
            int r = wm * 64 + (u >> 1) * 16 + (l >> 2) + 8 * (u & 1);
            dst[r] = rs[u];
        }
    }
    #pragma unroll
    for (int u = 0; u < 8; u++) rs[u] = 0.f;
}

__global__ void __launch_bounds__(256, 2) ntxent_main_kernel(const float* __restrict__ z) {
    extern __shared__ char sm[];
    const uint32_t s = smem_u32(sm);

    const int cta = blockIdx.x;
    const int tid = threadIdx.x;
    const int w = tid >> 5, l = tid & 31;
    const int wm = w >> 2, wn = w & 3;

    // ---- phase 1: f32 -> f16 convert (balanced slice) ----
    {
        const int TOT4 = N2 * DIM / 4;
        int i0 = (int)(((long long)cta * TOT4) / GRID_MAIN);
        int i1 = (int)(((long long)(cta + 1) * TOT4) / GRID_MAIN);
        for (int i = i0 + tid; i < i1; i += 256) {
            const float4 v = ((const float4*)z)[i];
            __half2 lo = __floats2half2_rn(v.x, v.y);
            __half2 hi = __floats2half2_rn(v.z, v.w);
            uint2 o;
            o.x = *(const uint32_t*)&lo;
            o.y = *(const uint32_t*)&hi;
            ((uint2*)g_zh)[i] = o;
        }
    }
    grid_barrier(&g_bar1, GRID_MAIN);

    // ---- phase 2: tournament HMMA sweep ----
    const int n0 = unit_n0(cta);
    const int n1 = unit_n0(cta + 1);

    const char* zh = (const char*)g_zh;
    const uint32_t laneA = (uint32_t)((l & 15) * ROWB + (l >> 4) * 16);
    const uint32_t laneB = (uint32_t)(((l & 7) + ((l >> 4) << 3)) * ROWB + (((l >> 3) & 1) << 4));
    const uint32_t A_warp = s + A_OFF + (uint32_t)wm * 64 * ROWB + laneA;

    int cur_rb, u0;
    decode_unit(n0, cur_rb, u0);
    prefetch_tile(s + A_OFF, zh + (size_t)cur_rb * 32768, tid);
    prefetch_tile(s + B0_OFF, zh + (size_t)((cur_rb + u0) & 127) * 32768, tid);
    asm volatile("cp.async.commit_group;" ::: "memory");

    // exact f32 positives in the cp.async shadow
    {
        int r0 = (int)(((long long)cta * N2) / GRID_MAIN);
        int r1 = (int)(((long long)(cta + 1) * N2) / GRID_MAIN);
        for (int row = r0 + w; row < r1; row += 8) {
            float4 a4 = ((const float4*)(z + (size_t)row * DIM))[l];
            float4 b4 = ((const float4*)(z + (size_t)(row ^ 8192) * DIM))[l];
            float d = fmaf(a4.x, b4.x, fmaf(a4.y, b4.y, fmaf(a4.z, b4.z, a4.w * b4.w)));
            #pragma unroll
            for (int off = 16; off >= 1; off >>= 1)
                d += __shfl_xor_sync(0xffffffffu, d, off);
            if (l == 0) g_pos[row] = 2.f * d;
        }
    }

    asm volatile("cp.async.wait_group 0;" ::: "memory");
    __syncthreads();

    float rs[8];
    #pragma unroll
    for (int u = 0; u < 8; u++) rs[u] = 0.f;
    int runidx = 0;
    int p = 0;

    for (int n = n0; n < n1; n++) {
        int rb, u;
        decode_unit(n, rb, u);

        __syncthreads();
        bool newA = (rb != cur_rb);
        if (newA) {
            flush_rows(rs, cta, runidx, wm, wn, l);
            runidx = 1;
            cur_rb = rb;
            prefetch_tile(s + A_OFF, zh + (size_t)rb * 32768, tid);
        }
        if (n + 1 < n1) {
            int rb2, u2;
            decode_unit(n + 1, rb2, u2);
            prefetch_tile(s + (p ? B0_OFF : B1_OFF),
                          zh + (size_t)((rb2 + u2) & 127) * 32768, tid);
        }
        asm volatile("cp.async.commit_group;" ::: "memory");
        if (newA) asm volatile("cp.async.wait_group 0;" ::: "memory");
        else      asm volatile("cp.async.wait_group 1;" ::: "memory");
        __syncthreads();

        const uint32_t B_warp = s + (p ? B1_OFF : B0_OFF)
                                  + (uint32_t)wn * 32 * ROWB + laneB;

        uint32_t acc[4][4][2];
        #pragma unroll
        for (int mf = 0; mf < 4; mf++)
            #pragma unroll
            for (int nf = 0; nf < 4; nf++) { acc[mf][nf][0] = 0u; acc[mf][nf][1] = 0u; }

        #pragma unroll
        for (int ks = 0; ks < 8; ks++) {
            uint32_t a[4][4], b[2][4];
            #pragma unroll
            for (int mf = 0; mf < 4; mf++)
                ldm_x4(a[mf], A_warp + mf * (16 * ROWB) + ks * 32);
            #pragma unroll
            for (int nh = 0; nh < 2; nh++)
                ldm_x4(b[nh], B_warp + nh * (16 * ROWB) + ks * 32);
            #pragma unroll
            for (int mf = 0; mf < 4; mf++)
                #pragma unroll
                for (int nf = 0; nf < 4; nf++)
                    mma_h(acc[mf][nf], a[mf], b[nf >> 1][(nf & 1) * 2],
                          b[nf >> 1][(nf & 1) * 2 + 1]);
        }

        if (u == 0) {
            #pragma unroll
            for (int mf = 0; mf < 4; mf++)
                #pragma unroll
                for (int nf = 0; nf < 4; nf++) {
                    float2 v0 = __half22float2(*(__half2*)&acc[mf][nf][0]);
                    float2 v1 = __half22float2(*(__half2*)&acc[mf][nf][1]);
                    int r = wm * 64 + mf * 16 + (l >> 2);
                    int c = wn * 32 + nf * 8 + 2 * (l & 3);
                    float e00 = (r == c)         ? 0.f : ex2(fmaf(v0.x, C1, -C1));
                    float e01 = (r == c + 1)     ? 0.f : ex2(fmaf(v0.y, C1, -C1));
                    float e10 = (r + 8 == c)     ? 0.f : ex2(fmaf(v1.x, C1, -C1));
                    float e11 = (r + 8 == c + 1) ? 0.f : ex2(fmaf(v1.y, C1, -C1));
                    rs[mf * 2]     += e00 + e01;
                    rs[mf * 2 + 1] += e10 + e11;
                }
        } else {
            float cs[8];
            #pragma unroll
            for (int v = 0; v < 8; v++) cs[v] = 0.f;
            #pragma unroll
            for (int mf = 0; mf < 4; mf++)
                #pragma unroll
                for (int nf = 0; nf < 4; nf++) {
                    float2 v0 = __half22float2(*(__half2*)&acc[mf][nf][0]);
                    float2 v1 = __half22float2(*(__half2*)&acc[mf][nf][1]);
                    float e00 = ex2(fmaf(v0.x, C1, -C1));
                    float e01 = ex2(fmaf(v0.y, C1, -C1));
                    float e10 = ex2(fmaf(v1.x, C1, -C1));
                    float e11 = ex2(fmaf(v1.y, C1, -C1));
                    rs[mf * 2]     += e00 + e01;
                    rs[mf * 2 + 1] += e10 + e11;
                    cs[nf * 2]     += e00 + e10;
                    cs[nf * 2 + 1] += e01 + e11;
                }
            #pragma unroll
            for (int v = 0; v < 8; v++) {
                cs[v] += __shfl_xor_sync(0xffffffffu, cs[v], 4);
                cs[v] += __shfl_xor_sync(0xffffffffu, cs[v], 8);
                cs[v] += __shfl_xor_sync(0xffffffffu, cs[v], 16);
            }
            if (l < 4) {
                float* dst = g_csp + (((size_t)rb * 64 + (u - 1)) * 2 + wm) * 128;
                #pragma unroll
                for (int v = 0; v < 8; v++) {
                    int c = wn * 32 + (v >> 1) * 8 + 2 * l + (v & 1);
                    dst[c] = cs[v];
                }
            }
        }
        p ^= 1;
    }

    flush_rows(rs, cta, runidx, wm, wn, l);
}

// 512 threads. Slice 0 additionally walks the closed-form covering-CTA range
// [cf, cl] for row-block j (<= ~4 CTAs); all 4 slices split the 64 d-values.
__global__ void __launch_bounds__(512) combine_kernel(float* __restrict__ out) {
    const int j = blockIdx.x;
    const int tid = threadIdx.x;
    const int r = tid & 127;
    const int sl = tid >> 7;
    float s = 0.f;

    if (sl == 0) {
        // unit range of rb j: [S, E]
        const int S = (j < 64) ? j * 65 : 4160 + (j - 64) * 64;
        const int E = S + ((j < 64) ? 64 : 63);
        // covering CTA range (balanced-split inverse, with fixups)
        int cf = (int)(((long long)S * GRID_MAIN) / NUNITS);
        while (unit_n0(cf + 1) <= S) cf++;
        while (cf > 0 && unit_n0(cf) > S) cf--;
        int cl = (int)(((long long)E * GRID_MAIN) / NUNITS) + 1;
        if (cl > GRID_MAIN - 1) cl = GRID_MAIN - 1;
        while (unit_n0(cl) > E) cl--;

        for (int c = cf; c <= cl; c++) {
            int na = unit_n0(c), nb = unit_n0(c + 1) - 1;
            int rb_a, ua, rb_b, ub;
            decode_unit(na, rb_a, ua);
            decode_unit(nb, rb_b, ub);
            if (rb_a == j) {
                const float* p = g_rowpart + ((size_t)c * 2 + 0) * 4 * 128;
                s += (p[r] + p[128 + r]) + (p[256 + r] + p[384 + r]);
            }
            if (rb_b == j && rb_b != rb_a) {
                const float* p = g_rowpart + ((size_t)c * 2 + 1) * 4 * 128;
                s += (p[r] + p[128 + r]) + (p[256 + r] + p[384 + r]);
            }
        }
    }
    #pragma unroll 4
    for (int dd = 0; dd < 16; dd++) {
        int d = sl * 16 + dd + 1;
        int rb = (j - d) & 127;
        if (d <= 63 || rb < 64) {
            const float* p = g_csp + (((size_t)rb * 64 + (d - 1)) * 2) * 128;
            s += p[r] + p[128 + r];
        }
    }

    __shared__ float part[4][128];
    __shared__ float red[128];
    part[sl][r] = s;
    __syncthreads();
    if (tid < 128) {
        float sum = (part[0][tid] + part[1][tid]) + (part[2][tid] + part[3][tid]);
        red[tid] = 2.f + logf(sum) - g_pos[j * 128 + tid];
    }
    __syncthreads();
    if (tid == 0) {
        float acc = 0.f;
        #pragma unroll 8
        for (int i = 0; i < 128; i++) acc += red[i];
        g_partials[j] = acc;
        __threadfence();
        int old = atomicAdd(&g_cnt, 1);
        if ((old & 127) == 127) {
            float tot = 0.f;
            for (int i = 0; i < 128; i++) tot += g_partials[i];
            *out = tot / (float)N2;
        }
    }
}

extern "C" void kernel_launch(void* const* d_in, const int* in_sizes, int n_in,
                              void* d_out, int out_size) {
    const float* z = (const float*)d_in[0];
    float* out = (float*)d_out;

    cudaFuncSetAttribute(ntxent_main_kernel,
                         cudaFuncAttributeMaxDynamicSharedMemorySize, SMEM_BYTES);

    ntxent_main_kernel<<<GRID_MAIN, 256, SMEM_BYTES>>>(z);
    combine_kernel<<<128, 512>>>(out);
}